// round 3
// baseline (speedup 1.0000x reference)
#include <cuda_runtime.h>
#include <math.h>

#define N_NODES 5000
#define E_EDGES 160000
#define F_HID   16

// ---- scratch (device globals: no allocation allowed) ----
__device__ float g_inv[N_NODES];            // deg -> rsqrt(deg)
__device__ float g_h1 [N_NODES * F_HID];    // x @ W1
__device__ float g_a1 [N_NODES * F_HID];    // A_hat @ h1
__device__ float g_hr [N_NODES * F_HID];    // relu(a1 + b1)
__device__ float g_p2 [N_NODES * F_HID];    // A_hat @ hr

// ---------------- degree / normalization ----------------
__global__ void k_deg_init() {
    int i = blockIdx.x * blockDim.x + threadIdx.x;
    if (i < N_NODES) g_inv[i] = 1.0f;   // self loop counts 1
}

__global__ void k_deg_edges(const int* __restrict__ dst) {
    int e = blockIdx.x * blockDim.x + threadIdx.x;
    if (e < E_EDGES) atomicAdd(&g_inv[dst[e]], 1.0f);
}

__global__ void k_rsqrt() {
    int i = blockIdx.x * blockDim.x + threadIdx.x;
    if (i < N_NODES) g_inv[i] = rsqrtf(g_inv[i]);
}

// ---------------- GEMM1: g_h1 = x[N,N] @ W1[N,16] ----------------
// Block = 256 threads (8 warps), 32 rows/block (4 rows/warp).
// W1 staged to smem transposed [j][kk] in chunks of 500 k's (conflict-free LDS).
#define G1_CH 500
__global__ void __launch_bounds__(256) k_gemm1(const float* __restrict__ x,
                                               const float* __restrict__ W1) {
    __shared__ float sW[F_HID * G1_CH];
    const int warp = threadIdx.x >> 5, lane = threadIdx.x & 31;
    const int row0 = blockIdx.x * 32 + warp * 4;

    float acc[4][16];
#pragma unroll
    for (int r = 0; r < 4; ++r)
#pragma unroll
        for (int j = 0; j < 16; ++j) acc[r][j] = 0.0f;

    for (int c = 0; c < N_NODES / G1_CH; ++c) {
        const int k0 = c * G1_CH;
        __syncthreads();
        for (int idx = threadIdx.x; idx < F_HID * G1_CH; idx += 256) {
            int kk = idx >> 4, j = idx & 15;
            sW[j * G1_CH + kk] = W1[(k0 + kk) * F_HID + j];
        }
        __syncthreads();

        for (int kk = lane; kk < G1_CH; kk += 32) {
            float xv[4];
#pragma unroll
            for (int r = 0; r < 4; ++r) {
                int row = row0 + r;
                xv[r] = (row < N_NODES) ? x[row * N_NODES + k0 + kk] : 0.0f;
            }
#pragma unroll
            for (int j = 0; j < 16; ++j) {
                float w = sW[j * G1_CH + kk];
#pragma unroll
                for (int r = 0; r < 4; ++r)
                    acc[r][j] = fmaf(xv[r], w, acc[r][j]);
            }
        }
    }

    // warp tree-reduce all 64 accumulators
#pragma unroll
    for (int r = 0; r < 4; ++r)
#pragma unroll
        for (int j = 0; j < 16; ++j)
#pragma unroll
            for (int o = 16; o; o >>= 1)
                acc[r][j] += __shfl_xor_sync(0xffffffffu, acc[r][j], o);

    if (lane == 0) {
#pragma unroll
        for (int r = 0; r < 4; ++r) {
            int row = row0 + r;
            if (row < N_NODES) {
#pragma unroll
                for (int j = 0; j < 16; ++j)
                    g_h1[row * F_HID + j] = acc[r][j];
            }
        }
    }
}

// ---------------- 16-wide propagation ----------------
__global__ void k_self1() {
    int t = blockIdx.x * blockDim.x + threadIdx.x;
    if (t >= N_NODES * F_HID) return;
    int i = t >> 4;
    float iv = g_inv[i];
    g_a1[t] = iv * iv * g_h1[t];
}

template <int L>
__global__ void k_edge_agg(const int* __restrict__ src, const int* __restrict__ dst) {
    int t = blockIdx.x * blockDim.x + threadIdx.x;
    if (t >= E_EDGES * F_HID) return;
    int e = t >> 4, j = t & 15;
    int s = src[e], d = dst[e];
    const float* feat  = (L == 1) ? g_h1 : g_hr;
    float*       accum = (L == 1) ? g_a1 : g_p2;
    float v = feat[s * F_HID + j] * g_inv[s] * g_inv[d];
    atomicAdd(&accum[d * F_HID + j], v);
}

__global__ void k_relu_self2(const float* __restrict__ b1) {
    int t = blockIdx.x * blockDim.x + threadIdx.x;
    if (t >= N_NODES * F_HID) return;
    int i = t >> 4, j = t & 15;
    float h = g_a1[t] + b1[j];
    h = fmaxf(h, 0.0f);
    g_hr[t] = h;
    float iv = g_inv[i];
    g_p2[t] = iv * iv * h;
}

// ---------------- GEMM2 + bias + log_softmax, fused ----------------
// Block = 256 threads, 8 full rows per block. z tile (8 x 5000 f32 = 160 KB)
// lives entirely in smem; p2 tile is register-resident per thread so the
// GEMM inner loop is pure LDG(W2, L2-hit) + FFMA. Then one warp per row does
// max / sum-exp / subtract and streams the final row to gmem.
__global__ void __launch_bounds__(256) k_gemm2(const float* __restrict__ W2,
                                               const float* __restrict__ b2,
                                               float* __restrict__ out) {
    extern __shared__ float sZ[];  // [8][N_NODES]
    const int row0 = blockIdx.x * 8;

    float p[8][16];
#pragma unroll
    for (int r = 0; r < 8; ++r)
#pragma unroll
        for (int k = 0; k < 16; ++k)
            p[r][k] = g_p2[(row0 + r) * F_HID + k];

    for (int c = threadIdx.x; c < N_NODES; c += 256) {
        float bv = b2[c];
        float acc[8];
#pragma unroll
        for (int r = 0; r < 8; ++r) acc[r] = bv;
#pragma unroll
        for (int k = 0; k < 16; ++k) {
            float w = W2[k * N_NODES + c];
#pragma unroll
            for (int r = 0; r < 8; ++r)
                acc[r] = fmaf(p[r][k], w, acc[r]);
        }
#pragma unroll
        for (int r = 0; r < 8; ++r) sZ[r * N_NODES + c] = acc[r];
    }
    __syncthreads();

    const int warp = threadIdx.x >> 5, lane = threadIdx.x & 31;
    const float* z = sZ + warp * N_NODES;

    float m = -INFINITY;
    for (int c = lane; c < N_NODES; c += 32) m = fmaxf(m, z[c]);
#pragma unroll
    for (int o = 16; o; o >>= 1) m = fmaxf(m, __shfl_xor_sync(0xffffffffu, m, o));

    float s = 0.0f;
    for (int c = lane; c < N_NODES; c += 32) s += __expf(z[c] - m);
#pragma unroll
    for (int o = 16; o; o >>= 1) s += __shfl_xor_sync(0xffffffffu, s, o);

    float lse = m + logf(s);
    float* orow = out + (size_t)(row0 + warp) * N_NODES;
    for (int c = lane; c < N_NODES; c += 32) orow[c] = z[c] - lse;
}

// ---------------- launch ----------------
extern "C" void kernel_launch(void* const* d_in, const int* in_sizes, int n_in,
                              void* d_out, int out_size) {
    const float* x   = (const float*)d_in[0];
    const int*   src = (const int*)  d_in[1];
    const int*   dst = (const int*)  d_in[2];
    const float* W1  = (const float*)d_in[3];
    const float* b1  = (const float*)d_in[4];
    const float* W2  = (const float*)d_in[5];
    const float* b2  = (const float*)d_in[6];
    float* out = (float*)d_out;

    const int smem2 = 8 * N_NODES * (int)sizeof(float);  // 160 KB
    cudaFuncSetAttribute(k_gemm2, cudaFuncAttributeMaxDynamicSharedMemorySize, smem2);

    k_deg_init <<<(N_NODES + 255) / 256, 256>>>();
    k_deg_edges<<<(E_EDGES + 255) / 256, 256>>>(dst);
    k_rsqrt    <<<(N_NODES + 255) / 256, 256>>>();

    k_gemm1<<<(N_NODES + 31) / 32, 256>>>(x, W1);

    k_self1<<<(N_NODES * F_HID + 255) / 256, 256>>>();
    k_edge_agg<1><<<(E_EDGES * F_HID + 255) / 256, 256>>>(src, dst);

    k_relu_self2<<<(N_NODES * F_HID + 255) / 256, 256>>>(b1);
    k_edge_agg<2><<<(E_EDGES * F_HID + 255) / 256, 256>>>(src, dst);

    k_gemm2<<<N_NODES / 8, 256, smem2>>>(W2, b2, out);
}